// round 14
// baseline (speedup 1.0000x reference)
#include <cuda_runtime.h>
#include <cuda_bf16.h>
#include <cuda_fp16.h>
#include <math.h>
#include <stdint.h>

#define D_MODEL 1024
#define S_LEN   2048
#define BATCH   2
#define NHEAD   16
#define DK      64
#define M_TOT   (BATCH * S_LEN)   // 4096
#define QSCALE  0.1803368801111244f   // (1/8) * log2(e)

// ---------------- scratch (device globals; no allocations allowed) ----------
__device__ __half g_Xh[M_TOT * D_MODEL];
__device__ __half g_Wq[D_MODEL * D_MODEL];
__device__ __half g_Wk[D_MODEL * D_MODEL];
__device__ __half g_Wv[D_MODEL * D_MODEL];
__device__ __half g_Wo[D_MODEL * D_MODEL];
__device__ __half g_Qh [M_TOT * D_MODEL];
__device__ __half g_Kh [M_TOT * D_MODEL];
__device__ __half g_Vh [M_TOT * D_MODEL];
__device__ __half g_attnh[M_TOT * D_MODEL];
__device__ float g_cos[S_LEN * 32];
__device__ float g_sin[S_LEN * 32];

// ---------------- common helpers --------------------------------------------
__device__ __forceinline__ uint32_t smem_u32(const void* p) {
    uint32_t a;
    asm("{ .reg .u64 t; cvta.to.shared.u64 t, %1; cvt.u32.u64 %0, t; }" : "=r"(a) : "l"(p));
    return a;
}

__device__ __forceinline__ float ex2f(float x) {
    float y;
    asm("ex2.approx.f32 %0, %1;" : "=f"(y) : "f"(x));
    return y;
}

__device__ __forceinline__ void ldsm_x4(uint32_t* r, uint32_t addr) {
    asm volatile("ldmatrix.sync.aligned.m8n8.x4.shared.b16 {%0,%1,%2,%3}, [%4];"
                 : "=r"(r[0]), "=r"(r[1]), "=r"(r[2]), "=r"(r[3]) : "r"(addr));
}

__device__ __forceinline__ void ldsm_x4t(uint32_t* r, uint32_t addr) {
    asm volatile("ldmatrix.sync.aligned.m8n8.x4.trans.shared.b16 {%0,%1,%2,%3}, [%4];"
                 : "=r"(r[0]), "=r"(r[1]), "=r"(r[2]), "=r"(r[3]) : "r"(addr));
}

__device__ __forceinline__ void mma_f16(float* c, const uint32_t* a,
                                        uint32_t b0, uint32_t b1) {
    asm volatile("mma.sync.aligned.m16n8k16.row.col.f32.f16.f16.f32 "
                 "{%0,%1,%2,%3}, {%4,%5,%6,%7}, {%8,%9}, {%0,%1,%2,%3};"
                 : "+f"(c[0]), "+f"(c[1]), "+f"(c[2]), "+f"(c[3])
                 : "r"(a[0]), "r"(a[1]), "r"(a[2]), "r"(a[3]), "r"(b0), "r"(b1));
}

__device__ __forceinline__ uint32_t pack2h(float a, float b) {
    union { __half2 h; uint32_t u; } c;
    c.h = __halves2half2(__float2half_rn(a), __float2half_rn(b));
    return c.u;
}

#define CP16(saddr, gptr) \
    asm volatile("cp.async.cg.shared.global [%0], [%1], 16;" :: "r"(saddr), "l"(gptr))
#define CP_COMMIT() asm volatile("cp.async.commit_group;" ::: "memory")
#define CP_WAIT0()  asm volatile("cp.async.wait_group 0;" ::: "memory")
#define CP_WAIT1()  asm volatile("cp.async.wait_group 1;" ::: "memory")

// ---------------- fused rope table + fp16 casts ------------------------------
__global__ void split_all(const float* __restrict__ x,  const float* __restrict__ Wq,
                          const float* __restrict__ Wk, const float* __restrict__ Wv,
                          const float* __restrict__ Wo)
{
    int t = blockIdx.x * blockDim.x + threadIdx.x;   // 0..2M-1
    if (t < S_LEN * 32) {
        int s = t >> 5, i = t & 31;
        float inv_freq = __expf(-(float)(2 * i) * (9.210340371976184f / 64.0f));
        float ang = (float)s * inv_freq;
        g_cos[t] = cosf(ang);
        g_sin[t] = sinf(ang);
    }
    const float* src;
    __half* dst;
    size_t off;
    if (t < (1 << 20)) { src = x; dst = g_Xh; off = t; }
    else {
        int r = t - (1 << 20);
        int w = r >> 18;
        off = (size_t)(r & ((1 << 18) - 1));
        if      (w == 0) { src = Wq; dst = g_Wq; }
        else if (w == 1) { src = Wk; dst = g_Wk; }
        else if (w == 2) { src = Wv; dst = g_Wv; }
        else             { src = Wo; dst = g_Wo; }
    }
    float4 v = ((const float4*)src)[off];
    uint2 o;
    o.x = pack2h(v.x, v.y);
    o.y = pack2h(v.z, v.w);
    ((uint2*)dst)[off] = o;
}

// ==== fp16 single-product GEMM (BK=64, 3-stage ring, pipelined ldsm) =========
#define GBK 64
#define GCHUNKS (D_MODEL / GBK)           // 16
#define GROWH  72                         // 144B row stride, conflict-free
#define GARR_B (128 * GROWH * 2)          // 18432
#define GSTG_B (2 * GARR_B)               // 36864 (A, B)
#define GSMEM_TOTAL (3 * GSTG_B)          // 110592

__device__ __forceinline__ void gemm_v7_core(
    const __half* __restrict__ A, const __half* __restrict__ B,
    int bm, int bn, float (&acc)[4][4][4])
{
    extern __shared__ char smem[];
    const uint32_t sb = smem_u32(smem);
    const int tid  = threadIdx.x;
    const int wid  = tid >> 5;
    const int lane = tid & 31;
    const int warp_m = (wid >> 2) * 64;
    const int warp_n = (wid & 3) * 32;

#pragma unroll
    for (int i = 0; i < 4; i++)
#pragma unroll
        for (int j = 0; j < 4; j++)
#pragma unroll
            for (int k = 0; k < 4; k++) acc[i][j][k] = 0.f;

    auto issue = [&](int stg, int c) {
        const uint32_t st = sb + stg * GSTG_B;
        const int k0 = c * GBK;
#pragma unroll
        for (int it = 0; it < 4; it++) {
            int slot = tid + it * 256;            // 0..1023
            int r  = slot >> 3;                   // 0..127
            int c8 = (slot & 7) * 8;              // halves
            uint32_t soff = (uint32_t)(r * GROWH + c8) * 2;
            size_t ga = (size_t)(bm + r) * D_MODEL + k0 + c8;
            size_t gb = (size_t)(bn + r) * D_MODEL + k0 + c8;
            CP16(st + soff,          (const char*)(A + ga));
            CP16(st + GARR_B + soff, (const char*)(B + gb));
        }
    };

    issue(0, 0);
    CP_COMMIT();
    issue(1, 1);
    CP_COMMIT();

    const int qrow = lane & 15;
    const int qcol = (lane >> 4) << 3;

    for (int c = 0; c < GCHUNKS; c++) {
        if (c + 1 < GCHUNKS) CP_WAIT1(); else CP_WAIT0();
        __syncthreads();
        if (c + 2 < GCHUNKS) { issue((c + 2) % 3, c + 2); CP_COMMIT(); }

        const uint32_t st = sb + (c % 3) * GSTG_B;
        const uint32_t aBase = st + (uint32_t)((warp_m + qrow) * GROWH + qcol) * 2;
        const uint32_t bBase = st + GARR_B + (uint32_t)((warp_n + qrow) * GROWH + qcol) * 2;

#pragma unroll
        for (int ks = 0; ks < 4; ks++) {
            const uint32_t ko = (uint32_t)(ks * 16) * 2;
            uint32_t bf[2][4];
            ldsm_x4(bf[0], bBase + ko);
            ldsm_x4(bf[1], bBase + (16 * GROWH * 2) + ko);
            // software-pipelined A fragments: af holds mi, an prefetches mi+1
            uint32_t af[4], an[4];
            ldsm_x4(af, aBase + ko);
#pragma unroll
            for (int mi = 0; mi < 4; mi++) {
                if (mi < 3)
                    ldsm_x4(an, aBase + (mi + 1) * (16 * GROWH * 2) + ko);
#pragma unroll
                for (int nt = 0; nt < 2; nt++)
#pragma unroll
                    for (int nj = 0; nj < 2; nj++)
                        mma_f16(acc[mi][nt * 2 + nj], af, bf[nt][nj], bf[nt][nj + 2]);
                if (mi < 3) {
                    af[0] = an[0]; af[1] = an[1]; af[2] = an[2]; af[3] = an[3];
                }
            }
        }
    }
}

// QKV GEMM: fused bias + RoPE; Q (log2e-scaled), K, V -> plain fp16
__global__ __launch_bounds__(256, 2)
void tc_qkv_v7(const float* __restrict__ bq, const float* __restrict__ bk,
               const float* __restrict__ bv)
{
    const int z = blockIdx.z;
    const __half* W;
    const float* bias;
    __half* D;
    if (z == 0)      { W = g_Wq; bias = bq; D = g_Qh; }
    else if (z == 1) { W = g_Wk; bias = bk; D = g_Kh; }
    else             { W = g_Wv; bias = bv; D = g_Vh; }

    const int bm = blockIdx.y * 128;
    const int bn = blockIdx.x * 128;
    float acc[4][4][4];
    gemm_v7_core(g_Xh, W, bm, bn, acc);

    const int wid  = threadIdx.x >> 5;
    const int lane = threadIdx.x & 31;
    const int warp_m = (wid >> 2) * 64;
    const int warp_n = (wid & 3) * 32;
    const int erow = lane >> 2;
    const int ecol = (lane & 3) * 2;

#pragma unroll
    for (int mi = 0; mi < 4; mi++)
#pragma unroll
        for (int nt = 0; nt < 2; nt++)
#pragma unroll
            for (int nj = 0; nj < 2; nj++) {
                float* cc = acc[mi][nt * 2 + nj];
                int m = bm + warp_m + mi * 16 + erow;
                int n = bn + warp_n + nt * 16 + nj * 8 + ecol;
                float v0 = cc[0] + bias[n], v1 = cc[1] + bias[n + 1];
                float w0 = cc[2] + bias[n], w1 = cc[3] + bias[n + 1];
                if (z < 2) {
                    int i  = (n & 63) >> 1;
                    int s0 = (m & 2047) * 32 + i;
                    int s1 = ((m + 8) & 2047) * 32 + i;
                    float cs0 = g_cos[s0], sn0 = g_sin[s0];
                    float cs1 = g_cos[s1], sn1 = g_sin[s1];
                    float t0 = v0 * cs0 - v1 * sn0, t1 = v0 * sn0 + v1 * cs0;
                    float u0 = w0 * cs1 - w1 * sn1, u1 = w0 * sn1 + w1 * cs1;
                    if (z == 0) { t0 *= QSCALE; t1 *= QSCALE; u0 *= QSCALE; u1 *= QSCALE; }
                    v0 = t0; v1 = t1; w0 = u0; w1 = u1;
                }
                size_t o0 = (size_t)m * D_MODEL + n;
                size_t o1 = (size_t)(m + 8) * D_MODEL + n;
                *(uint32_t*)(D + o0) = pack2h(v0, v1);
                *(uint32_t*)(D + o1) = pack2h(w0, w1);
            }
}

__global__ __launch_bounds__(256, 2)
void tc_out_v7(const float* __restrict__ bo, float* __restrict__ out)
{
    const int bm = blockIdx.y * 128;
    const int bn = blockIdx.x * 128;
    float acc[4][4][4];
    gemm_v7_core(g_attnh, g_Wo, bm, bn, acc);

    const int wid  = threadIdx.x >> 5;
    const int lane = threadIdx.x & 31;
    const int warp_m = (wid >> 2) * 64;
    const int warp_n = (wid & 3) * 32;
    const int erow = lane >> 2;
    const int ecol = (lane & 3) * 2;

#pragma unroll
    for (int mi = 0; mi < 4; mi++)
#pragma unroll
        for (int nt = 0; nt < 2; nt++)
#pragma unroll
            for (int nj = 0; nj < 2; nj++) {
                float* cc = acc[mi][nt * 2 + nj];
                int m = bm + warp_m + mi * 16 + erow;
                int n = bn + warp_n + nt * 16 + nj * 8 + ecol;
                float2 v0 = make_float2(cc[0] + bo[n], cc[1] + bo[n + 1]);
                float2 v1 = make_float2(cc[2] + bo[n], cc[3] + bo[n + 1]);
                *(float2*)(out + (size_t)m * D_MODEL + n)       = v0;
                *(float2*)(out + (size_t)(m + 8) * D_MODEL + n) = v1;
            }
}

// ---- attention: 4 warps x 32 rows, pipelined ldsm, 3-stage ring -------------
#define AROW   72
#define A_ARR  (64 * AROW * 2)            // 9216
#define AQ_ARR (128 * AROW * 2)           // 18432
#define SQ_OFF 0
#define STG0   AQ_ARR                     // 18432
#define ASTG_B (2 * A_ARR)                // 18432 (Kh, Vh)
#define A_SMEM (AQ_ARR + 3 * ASTG_B)      // 73728

__global__ __launch_bounds__(128, 3)
void attn_mma_kernel()
{
    extern __shared__ char smem[];
    const uint32_t sb = smem_u32(smem);
    const int tid  = threadIdx.x;
    const int wid  = tid >> 5;                 // 0..3
    const int lane = tid & 31;
    const int qb = (int)gridDim.x - 1 - (int)blockIdx.x;
    const int bh = blockIdx.y;
    const int b  = bh >> 4;
    const int h  = bh & 15;
    const int q0 = qb * 128;

    const size_t qgbase = (size_t)(b * S_LEN + q0) * D_MODEL + h * DK;
    const size_t kgbase = (size_t)(b * S_LEN) * D_MODEL + h * DK;

    auto issue_tile = [&](int stg, int kt) {
        const uint32_t sbase = sb + STG0 + stg * ASTG_B;
        const size_t g0 = kgbase + (size_t)(kt * 64) * D_MODEL;
#pragma unroll
        for (int it = 0; it < 4; it++) {
            int slot = tid + it * 128;         // 0..511
            int r  = slot >> 3;                // 0..63
            int c8 = (slot & 7) * 8;
            uint32_t soff = (uint32_t)(r * AROW + c8) * 2;
            const size_t go = g0 + (size_t)r * D_MODEL + c8;
            CP16(sbase + soff,         (const char*)(g_Kh + go));
            CP16(sbase + A_ARR + soff, (const char*)(g_Vh + go));
        }
    };

    const int ntiles = 2 * qb + 2;

    issue_tile(0, 0);
    CP_COMMIT();
    issue_tile(1, 1);
    CP_COMMIT();

    // load Q tile (128 rows)
#pragma unroll
    for (int it = 0; it < 8; it++) {
        int slot = tid + it * 128;             // 0..1023
        int r  = slot >> 3;                    // 0..127
        int c8 = (slot & 7) * 8;
        uint32_t soff = (uint32_t)(r * AROW + c8) * 2;
        const size_t go = qgbase + (size_t)r * D_MODEL + c8;
        *(uint4*)(smem + SQ_OFF + soff) = *(const uint4*)(g_Qh + go);
    }

    float oa0[8][4], oa1[8][4];
#pragma unroll
    for (int nt = 0; nt < 8; nt++)
#pragma unroll
        for (int j = 0; j < 4; j++) { oa0[nt][j] = 0.f; oa1[nt][j] = 0.f; }
    float m0 = -1e30f, m1 = -1e30f, m2 = -1e30f, m3 = -1e30f;
    float l0 = 0.f, l1 = 0.f, l2 = 0.f, l3 = 0.f;

    const int wrow_min = q0 + wid * 32;
    const int row_a = wrow_min + (lane >> 2);
    const int row_b = row_a + 16;

    const uint32_t qBase0 = sb + SQ_OFF +
        (uint32_t)((wid * 32 + (lane & 15)) * AROW + ((lane >> 4) << 3)) * 2;
    const uint32_t qBase1 = qBase0 + (uint32_t)(16 * AROW) * 2;

    for (int kt = 0; kt < ntiles; kt++) {
        if (kt + 1 < ntiles) CP_WAIT1(); else CP_WAIT0();
        __syncthreads();
        if (kt + 2 < ntiles) { issue_tile((kt + 2) % 3, kt + 2); CP_COMMIT(); }

        if (kt * 64 > wrow_min + 31) continue;

        const uint32_t st = sb + STG0 + (kt % 3) * ASTG_B;

        float s0[8][4], s1[8][4];
#pragma unroll
        for (int nt = 0; nt < 8; nt++)
#pragma unroll
            for (int j = 0; j < 4; j++) { s0[nt][j] = 0.f; s1[nt][j] = 0.f; }

        // S = Q @ K^T, software-pipelined K ldsm across the flattened (t,g) loop
        {
            const uint32_t kcol = (uint32_t)((lane & 15) * AROW + ((lane >> 4) << 3)) * 2;
            uint32_t kf[4], kn[4];
            uint32_t q0f[4], q1f[4], q0n[4], q1n[4];
            ldsm_x4(kf, st + kcol);                       // (t0,g0)
            ldsm_x4(q0f, qBase0);
            ldsm_x4(q1f, qBase1);
#pragma unroll
            for (int t = 0; t < 4; t++) {
                if (t < 3) {
                    ldsm_x4(q0n, qBase0 + (uint32_t)((t + 1) * 16) * 2);
                    ldsm_x4(q1n, qBase1 + (uint32_t)((t + 1) * 16) * 2);
                }
#pragma unroll
                for (int g = 0; g < 4; g++) {
                    // prefetch next K fragment before current mma block
                    int ng = (g + 1) & 3;
                    int nt2 = (g == 3) ? t + 1 : t;
                    if (!(t == 3 && g == 3))
                        ldsm_x4(kn, st + (uint32_t)(ng * 16 * AROW * 2) + nt2 * 32 + kcol);
                    mma_f16(s0[2 * g],     q0f, kf[0], kf[2]);
                    mma_f16(s0[2 * g + 1], q0f, kf[1], kf[3]);
                    mma_f16(s1[2 * g],     q1f, kf[0], kf[2]);
                    mma_f16(s1[2 * g + 1], q1f, kf[1], kf[3]);
                    kf[0] = kn[0]; kf[1] = kn[1]; kf[2] = kn[2]; kf[3] = kn[3];
                }
                q0f[0] = q0n[0]; q0f[1] = q0n[1]; q0f[2] = q0n[2]; q0f[3] = q0n[3];
                q1f[0] = q1n[0]; q1f[1] = q1n[1]; q1f[2] = q1n[2]; q1f[3] = q1n[3];
            }
        }

        if (kt * 64 + 63 > wrow_min) {
#pragma unroll
            for (int nt = 0; nt < 8; nt++) {
                int col = kt * 64 + nt * 8 + (lane & 3) * 2;
                if (col     > row_a)     s0[nt][0] = -1e30f;
                if (col + 1 > row_a)     s0[nt][1] = -1e30f;
                if (col     > row_a + 8) s0[nt][2] = -1e30f;
                if (col + 1 > row_a + 8) s0[nt][3] = -1e30f;
                if (col     > row_b)     s1[nt][0] = -1e30f;
                if (col + 1 > row_b)     s1[nt][1] = -1e30f;
                if (col     > row_b + 8) s1[nt][2] = -1e30f;
                if (col + 1 > row_b + 8) s1[nt][3] = -1e30f;
            }
        }

        // ---- online softmax, both groups ----
        float x0 = -1e30f, x1 = -1e30f, x2 = -1e30f, x3 = -1e30f;
#pragma unroll
        for (int nt = 0; nt < 8; nt++) {
            x0 = fmaxf(x0, fmaxf(s0[nt][0], s0[nt][1]));
            x1 = fmaxf(x1, fmaxf(s0[nt][2], s0[nt][3]));
            x2 = fmaxf(x2, fmaxf(s1[nt][0], s1[nt][1]));
            x3 = fmaxf(x3, fmaxf(s1[nt][2], s1[nt][3]));
        }
        x0 = fmaxf(x0, __shfl_xor_sync(0xffffffffu, x0, 1));
        x0 = fmaxf(x0, __shfl_xor_sync(0xffffffffu, x0, 2));
        x1 = fmaxf(x1, __shfl_xor_sync(0xffffffffu, x1, 1));
        x1 = fmaxf(x1, __shfl_xor_sync(0xffffffffu, x1, 2));
        x2 = fmaxf(x2, __shfl_xor_sync(0xffffffffu, x2, 1));
        x2 = fmaxf(x2, __shfl_xor_sync(0xffffffffu, x2, 2));
        x3 = fmaxf(x3, __shfl_xor_sync(0xffffffffu, x3, 1));
        x3 = fmaxf(x3, __shfl_xor_sync(0xffffffffu, x3, 2));

        float n0 = fmaxf(m0, x0), n1 = fmaxf(m1, x1);
        float n2 = fmaxf(m2, x2), n3 = fmaxf(m3, x3);
        float c0 = ex2f(m0 - n0), c1 = ex2f(m1 - n1);
        float c2 = ex2f(m2 - n2), c3 = ex2f(m3 - n3);
        m0 = n0; m1 = n1; m2 = n2; m3 = n3;

        float u0 = 0.f, u1 = 0.f, u2 = 0.f, u3 = 0.f;
#pragma unroll
        for (int nt = 0; nt < 8; nt++) {
            s0[nt][0] = ex2f(s0[nt][0] - n0);
            s0[nt][1] = ex2f(s0[nt][1] - n0);
            s0[nt][2] = ex2f(s0[nt][2] - n1);
            s0[nt][3] = ex2f(s0[nt][3] - n1);
            s1[nt][0] = ex2f(s1[nt][0] - n2);
            s1[nt][1] = ex2f(s1[nt][1] - n2);
            s1[nt][2] = ex2f(s1[nt][2] - n3);
            s1[nt][3] = ex2f(s1[nt][3] - n3);
            u0 += s0[nt][0] + s0[nt][1];
            u1 += s0[nt][2] + s0[nt][3];
            u2 += s1[nt][0] + s1[nt][1];
            u3 += s1[nt][2] + s1[nt][3];
        }
        u0 += __shfl_xor_sync(0xffffffffu, u0, 1);
        u0 += __shfl_xor_sync(0xffffffffu, u0, 2);
        u1 += __shfl_xor_sync(0xffffffffu, u1, 1);
        u1 += __shfl_xor_sync(0xffffffffu, u1, 2);
        u2 += __shfl_xor_sync(0xffffffffu, u2, 1);
        u2 += __shfl_xor_sync(0xffffffffu, u2, 2);
        u3 += __shfl_xor_sync(0xffffffffu, u3, 1);
        u3 += __shfl_xor_sync(0xffffffffu, u3, 2);
        l0 = l0 * c0 + u0;
        l1 = l1 * c1 + u1;
        l2 = l2 * c2 + u2;
        l3 = l3 * c3 + u3;

#pragma unroll
        for (int nt = 0; nt < 8; nt++) {
            oa0[nt][0] *= c0; oa0[nt][1] *= c0;
            oa0[nt][2] *= c1; oa0[nt][3] *= c1;
            oa1[nt][0] *= c2; oa1[nt][1] *= c2;
            oa1[nt][2] *= c3; oa1[nt][3] *= c3;
        }

        uint32_t p0[4][4], p1[4][4];
#pragma unroll
        for (int t = 0; t < 4; t++) {
            p0[t][0] = pack2h(s0[2 * t][0],     s0[2 * t][1]);
            p0[t][1] = pack2h(s0[2 * t][2],     s0[2 * t][3]);
            p0[t][2] = pack2h(s0[2 * t + 1][0], s0[2 * t + 1][1]);
            p0[t][3] = pack2h(s0[2 * t + 1][2], s0[2 * t + 1][3]);
            p1[t][0] = pack2h(s1[2 * t][0],     s1[2 * t][1]);
            p1[t][1] = pack2h(s1[2 * t][2],     s1[2 * t][3]);
            p1[t][2] = pack2h(s1[2 * t + 1][0], s1[2 * t + 1][1]);
            p1[t][3] = pack2h(s1[2 * t + 1][2], s1[2 * t + 1][3]);
        }

        // O += P @ V, software-pipelined V ldsm across flattened (t,g) loop
        {
            const uint32_t vcol = (uint32_t)(((lane & 7) + ((lane >> 3) & 1) * 8) * AROW +
                                             ((lane >> 4) << 3)) * 2;
            uint32_t vf[4], vn[4];
            ldsm_x4t(vf, st + A_ARR + vcol);             // (t0,g0)
#pragma unroll
            for (int t = 0; t < 4; t++) {
#pragma unroll
                for (int g = 0; g < 4; g++) {
                    int ng = (g + 1) & 3;
                    int nt2 = (g == 3) ? t + 1 : t;
                    if (!(t == 3 && g == 3))
                        ldsm_x4t(vn, st + A_ARR + (uint32_t)(nt2 * 16 * AROW * 2) +
                                 (uint32_t)(ng * 16) * 2 + vcol);
                    mma_f16(oa0[2 * g],     p0[t], vf[0], vf[1]);
                    mma_f16(oa0[2 * g + 1], p0[t], vf[2], vf[3]);
                    mma_f16(oa1[2 * g],     p1[t], vf[0], vf[1]);
                    mma_f16(oa1[2 * g + 1], p1[t], vf[2], vf[3]);
                    vf[0] = vn[0]; vf[1] = vn[1]; vf[2] = vn[2]; vf[3] = vn[3];
                }
            }
        }
    }

    // ---- epilogue: normalize + fp16 to global (for out-proj) ----
    float i0 = 1.0f / l0, i1 = 1.0f / l1, i2 = 1.0f / l2, i3 = 1.0f / l3;
    size_t ba0 = (size_t)(b * S_LEN + row_a) * D_MODEL + h * DK;
    size_t ba1 = ba0 + (size_t)8 * D_MODEL;
    size_t bb0 = (size_t)(b * S_LEN + row_b) * D_MODEL + h * DK;
    size_t bb1 = bb0 + (size_t)8 * D_MODEL;
#pragma unroll
    for (int nt = 0; nt < 8; nt++) {
        int col = nt * 8 + (lane & 3) * 2;
        *(uint32_t*)(g_attnh + ba0 + col) = pack2h(oa0[nt][0] * i0, oa0[nt][1] * i0);
        *(uint32_t*)(g_attnh + ba1 + col) = pack2h(oa0[nt][2] * i1, oa0[nt][3] * i1);
        *(uint32_t*)(g_attnh + bb0 + col) = pack2h(oa1[nt][0] * i2, oa1[nt][1] * i2);
        *(uint32_t*)(g_attnh + bb1 + col) = pack2h(oa1[nt][2] * i3, oa1[nt][3] * i3);
    }
}

// ---------------- launch ------------------------------------------------------
extern "C" void kernel_launch(void* const* d_in, const int* in_sizes, int n_in,
                              void* d_out, int out_size)
{
    const float* x  = (const float*)d_in[0];
    const float* Wq = (const float*)d_in[1];
    const float* bq = (const float*)d_in[2];
    const float* Wk = (const float*)d_in[3];
    const float* bk = (const float*)d_in[4];
    const float* Wv = (const float*)d_in[5];
    const float* bv = (const float*)d_in[6];
    const float* Wo = (const float*)d_in[7];
    const float* bo = (const float*)d_in[8];
    float* out = (float*)d_out;

    static int configured = 0;
    if (!configured) {
        cudaFuncSetAttribute(tc_qkv_v7, cudaFuncAttributeMaxDynamicSharedMemorySize, GSMEM_TOTAL);
        cudaFuncSetAttribute(tc_out_v7, cudaFuncAttributeMaxDynamicSharedMemorySize, GSMEM_TOTAL);
        cudaFuncSetAttribute(attn_mma_kernel, cudaFuncAttributeMaxDynamicSharedMemorySize, A_SMEM);
        configured = 1;
    }

    // 0) fused rope table + fp16 casts of x and weights
    split_all<<<(2 * 1024 * 1024) / 256, 256>>>(x, Wq, Wk, Wv, Wo);

    // 1) QKV projections (single-product fp16, pipelined ldsm) + RoPE epilogue
    dim3 g_qkv(D_MODEL / 128, M_TOT / 128, 3);
    tc_qkv_v7<<<g_qkv, 256, GSMEM_TOTAL>>>(bq, bk, bv);

    // 2) causal attention (4 warps x 32 rows, pipelined ldsm, 3-stage ring)
    dim3 g_att(S_LEN / 128, BATCH * NHEAD);
    attn_mma_kernel<<<g_att, 128, A_SMEM>>>();

    // 3) output projection (single-product fp16, pipelined ldsm)
    dim3 g_out(D_MODEL / 128, M_TOT / 128);
    tc_out_v7<<<g_out, 256, GSMEM_TOTAL>>>(bo, out);
}

// round 15
// speedup vs baseline: 1.5537x; 1.5537x over previous
#include <cuda_runtime.h>
#include <cuda_bf16.h>
#include <cuda_fp16.h>
#include <math.h>
#include <stdint.h>

#define D_MODEL 1024
#define S_LEN   2048
#define BATCH   2
#define NHEAD   16
#define DK      64
#define M_TOT   (BATCH * S_LEN)   // 4096
#define QSCALE  0.1803368801111244f   // (1/8) * log2(e)

// ---------------- scratch (device globals; no allocations allowed) ----------
__device__ __half g_Xh[M_TOT * D_MODEL];
__device__ __half g_Wq[D_MODEL * D_MODEL];
__device__ __half g_Wk[D_MODEL * D_MODEL];
__device__ __half g_Wv[D_MODEL * D_MODEL];
__device__ __half g_Wo[D_MODEL * D_MODEL];
__device__ __half g_Qh [M_TOT * D_MODEL];
__device__ __half g_Kh [M_TOT * D_MODEL];
__device__ __half g_Vh [M_TOT * D_MODEL];
__device__ __half g_attnh[M_TOT * D_MODEL];
__device__ float g_cos[S_LEN * 32];
__device__ float g_sin[S_LEN * 32];

// ---------------- common helpers --------------------------------------------
__device__ __forceinline__ uint32_t smem_u32(const void* p) {
    uint32_t a;
    asm("{ .reg .u64 t; cvta.to.shared.u64 t, %1; cvt.u32.u64 %0, t; }" : "=r"(a) : "l"(p));
    return a;
}

__device__ __forceinline__ float ex2f(float x) {
    float y;
    asm("ex2.approx.f32 %0, %1;" : "=f"(y) : "f"(x));
    return y;
}

__device__ __forceinline__ void ldsm_x4(uint32_t* r, uint32_t addr) {
    asm volatile("ldmatrix.sync.aligned.m8n8.x4.shared.b16 {%0,%1,%2,%3}, [%4];"
                 : "=r"(r[0]), "=r"(r[1]), "=r"(r[2]), "=r"(r[3]) : "r"(addr));
}

__device__ __forceinline__ void ldsm_x4t(uint32_t* r, uint32_t addr) {
    asm volatile("ldmatrix.sync.aligned.m8n8.x4.trans.shared.b16 {%0,%1,%2,%3}, [%4];"
                 : "=r"(r[0]), "=r"(r[1]), "=r"(r[2]), "=r"(r[3]) : "r"(addr));
}

__device__ __forceinline__ void mma_f16(float* c, const uint32_t* a,
                                        uint32_t b0, uint32_t b1) {
    asm volatile("mma.sync.aligned.m16n8k16.row.col.f32.f16.f16.f32 "
                 "{%0,%1,%2,%3}, {%4,%5,%6,%7}, {%8,%9}, {%0,%1,%2,%3};"
                 : "+f"(c[0]), "+f"(c[1]), "+f"(c[2]), "+f"(c[3])
                 : "r"(a[0]), "r"(a[1]), "r"(a[2]), "r"(a[3]), "r"(b0), "r"(b1));
}

__device__ __forceinline__ uint32_t pack2h(float a, float b) {
    union { __half2 h; uint32_t u; } c;
    c.h = __halves2half2(__float2half_rn(a), __float2half_rn(b));
    return c.u;
}

#define CP16(saddr, gptr) \
    asm volatile("cp.async.cg.shared.global [%0], [%1], 16;" :: "r"(saddr), "l"(gptr))
#define CP_COMMIT() asm volatile("cp.async.commit_group;" ::: "memory")
#define CP_WAIT0()  asm volatile("cp.async.wait_group 0;" ::: "memory")
#define CP_WAIT1()  asm volatile("cp.async.wait_group 1;" ::: "memory")

// ---------------- fused rope table + fp16 casts ------------------------------
__global__ void split_all(const float* __restrict__ x,  const float* __restrict__ Wq,
                          const float* __restrict__ Wk, const float* __restrict__ Wv,
                          const float* __restrict__ Wo)
{
    int t = blockIdx.x * blockDim.x + threadIdx.x;   // 0..2M-1
    if (t < S_LEN * 32) {
        int s = t >> 5, i = t & 31;
        float inv_freq = __expf(-(float)(2 * i) * (9.210340371976184f / 64.0f));
        float ang = (float)s * inv_freq;
        g_cos[t] = cosf(ang);
        g_sin[t] = sinf(ang);
    }
    const float* src;
    __half* dst;
    size_t off;
    if (t < (1 << 20)) { src = x; dst = g_Xh; off = t; }
    else {
        int r = t - (1 << 20);
        int w = r >> 18;
        off = (size_t)(r & ((1 << 18) - 1));
        if      (w == 0) { src = Wq; dst = g_Wq; }
        else if (w == 1) { src = Wk; dst = g_Wk; }
        else if (w == 2) { src = Wv; dst = g_Wv; }
        else             { src = Wo; dst = g_Wo; }
    }
    float4 v = ((const float4*)src)[off];
    uint2 o;
    o.x = pack2h(v.x, v.y);
    o.y = pack2h(v.z, v.w);
    ((uint2*)dst)[off] = o;
}

// ========== fp16 single-product GEMM (BK=64, 3-stage cp.async ring) ==========
#define GBK 64
#define GCHUNKS (D_MODEL / GBK)           // 16
#define GROWH  72                         // 144B row stride, conflict-free
#define GARR_B (128 * GROWH * 2)          // 18432
#define GSTG_B (2 * GARR_B)               // 36864 (A, B)
#define GSMEM_TOTAL (3 * GSTG_B)          // 110592

__device__ __forceinline__ void gemm_v5_core(
    const __half* __restrict__ A, const __half* __restrict__ B,
    int bm, int bn, float (&acc)[4][4][4])
{
    extern __shared__ char smem[];
    const uint32_t sb = smem_u32(smem);
    const int tid  = threadIdx.x;
    const int wid  = tid >> 5;
    const int lane = tid & 31;
    const int warp_m = (wid >> 2) * 64;
    const int warp_n = (wid & 3) * 32;

#pragma unroll
    for (int i = 0; i < 4; i++)
#pragma unroll
        for (int j = 0; j < 4; j++)
#pragma unroll
            for (int k = 0; k < 4; k++) acc[i][j][k] = 0.f;

    auto issue = [&](int stg, int c) {
        const uint32_t st = sb + stg * GSTG_B;
        const int k0 = c * GBK;
#pragma unroll
        for (int it = 0; it < 4; it++) {
            int slot = tid + it * 256;            // 0..1023
            int r  = slot >> 3;                   // 0..127
            int c8 = (slot & 7) * 8;              // halves
            uint32_t soff = (uint32_t)(r * GROWH + c8) * 2;
            size_t ga = (size_t)(bm + r) * D_MODEL + k0 + c8;
            size_t gb = (size_t)(bn + r) * D_MODEL + k0 + c8;
            CP16(st + soff,          (const char*)(A + ga));
            CP16(st + GARR_B + soff, (const char*)(B + gb));
        }
    };

    issue(0, 0);
    CP_COMMIT();
    issue(1, 1);
    CP_COMMIT();

    const int qrow = lane & 15;
    const int qcol = (lane >> 4) << 3;

    for (int c = 0; c < GCHUNKS; c++) {
        if (c + 1 < GCHUNKS) CP_WAIT1(); else CP_WAIT0();
        __syncthreads();
        if (c + 2 < GCHUNKS) { issue((c + 2) % 3, c + 2); CP_COMMIT(); }

        const uint32_t st = sb + (c % 3) * GSTG_B;
        const uint32_t aBase = st + (uint32_t)((warp_m + qrow) * GROWH + qcol) * 2;
        const uint32_t bBase = st + GARR_B + (uint32_t)((warp_n + qrow) * GROWH + qcol) * 2;

#pragma unroll
        for (int ks = 0; ks < 4; ks++) {
            const uint32_t ko = (uint32_t)(ks * 16) * 2;
            uint32_t bf[2][4];
#pragma unroll
            for (int nt = 0; nt < 2; nt++)
                ldsm_x4(bf[nt], bBase + nt * (16 * GROWH * 2) + ko);
#pragma unroll
            for (int mi = 0; mi < 4; mi++) {
                uint32_t af[4];
                ldsm_x4(af, aBase + mi * (16 * GROWH * 2) + ko);
#pragma unroll
                for (int nt = 0; nt < 2; nt++)
#pragma unroll
                    for (int nj = 0; nj < 2; nj++)
                        mma_f16(acc[mi][nt * 2 + nj], af, bf[nt][nj], bf[nt][nj + 2]);
            }
        }
    }
}

// QKV GEMM: fused bias + RoPE; Q (log2e-scaled), K, V -> plain fp16
__global__ __launch_bounds__(256, 2)
void tc_qkv_v6(const float* __restrict__ bq, const float* __restrict__ bk,
               const float* __restrict__ bv)
{
    const int z = blockIdx.z;
    const __half* W;
    const float* bias;
    __half* D;
    if (z == 0)      { W = g_Wq; bias = bq; D = g_Qh; }
    else if (z == 1) { W = g_Wk; bias = bk; D = g_Kh; }
    else             { W = g_Wv; bias = bv; D = g_Vh; }

    const int bm = blockIdx.y * 128;
    const int bn = blockIdx.x * 128;
    float acc[4][4][4];
    gemm_v5_core(g_Xh, W, bm, bn, acc);

    const int wid  = threadIdx.x >> 5;
    const int lane = threadIdx.x & 31;
    const int warp_m = (wid >> 2) * 64;
    const int warp_n = (wid & 3) * 32;
    const int erow = lane >> 2;
    const int ecol = (lane & 3) * 2;

#pragma unroll
    for (int mi = 0; mi < 4; mi++)
#pragma unroll
        for (int nt = 0; nt < 2; nt++)
#pragma unroll
            for (int nj = 0; nj < 2; nj++) {
                float* cc = acc[mi][nt * 2 + nj];
                int m = bm + warp_m + mi * 16 + erow;
                int n = bn + warp_n + nt * 16 + nj * 8 + ecol;
                float v0 = cc[0] + bias[n], v1 = cc[1] + bias[n + 1];
                float w0 = cc[2] + bias[n], w1 = cc[3] + bias[n + 1];
                if (z < 2) {
                    int i  = (n & 63) >> 1;
                    int s0 = (m & 2047) * 32 + i;
                    int s1 = ((m + 8) & 2047) * 32 + i;
                    float cs0 = g_cos[s0], sn0 = g_sin[s0];
                    float cs1 = g_cos[s1], sn1 = g_sin[s1];
                    float t0 = v0 * cs0 - v1 * sn0, t1 = v0 * sn0 + v1 * cs0;
                    float u0 = w0 * cs1 - w1 * sn1, u1 = w0 * sn1 + w1 * cs1;
                    if (z == 0) { t0 *= QSCALE; t1 *= QSCALE; u0 *= QSCALE; u1 *= QSCALE; }
                    v0 = t0; v1 = t1; w0 = u0; w1 = u1;
                }
                size_t o0 = (size_t)m * D_MODEL + n;
                size_t o1 = (size_t)(m + 8) * D_MODEL + n;
                *(uint32_t*)(D + o0) = pack2h(v0, v1);
                *(uint32_t*)(D + o1) = pack2h(w0, w1);
            }
}

__global__ __launch_bounds__(256, 2)
void tc_out_v6(const float* __restrict__ bo, float* __restrict__ out)
{
    const int bm = blockIdx.y * 128;
    const int bn = blockIdx.x * 128;
    float acc[4][4][4];
    gemm_v5_core(g_attnh, g_Wo, bm, bn, acc);

    const int wid  = threadIdx.x >> 5;
    const int lane = threadIdx.x & 31;
    const int warp_m = (wid >> 2) * 64;
    const int warp_n = (wid & 3) * 32;
    const int erow = lane >> 2;
    const int ecol = (lane & 3) * 2;

#pragma unroll
    for (int mi = 0; mi < 4; mi++)
#pragma unroll
        for (int nt = 0; nt < 2; nt++)
#pragma unroll
            for (int nj = 0; nj < 2; nj++) {
                float* cc = acc[mi][nt * 2 + nj];
                int m = bm + warp_m + mi * 16 + erow;
                int n = bn + warp_n + nt * 16 + nj * 8 + ecol;
                float2 v0 = make_float2(cc[0] + bo[n], cc[1] + bo[n + 1]);
                float2 v1 = make_float2(cc[2] + bo[n], cc[3] + bo[n + 1]);
                *(float2*)(out + (size_t)m * D_MODEL + n)       = v0;
                *(float2*)(out + (size_t)(m + 8) * D_MODEL + n) = v1;
            }
}

// ---- attention: 4 warps x 32 rows, single fp16 Q, 3-stage ring --------------
#define AROW   72
#define A_ARR  (64 * AROW * 2)            // 9216
#define AQ_ARR (128 * AROW * 2)           // 18432
#define SQ_OFF 0
#define STG0   AQ_ARR                     // 18432
#define ASTG_B (2 * A_ARR)                // 18432 (Kh, Vh)
#define A_SMEM (AQ_ARR + 3 * ASTG_B)      // 73728

__global__ __launch_bounds__(128, 3)
void attn_mma_kernel()
{
    extern __shared__ char smem[];
    const uint32_t sb = smem_u32(smem);
    const int tid  = threadIdx.x;
    const int wid  = tid >> 5;                 // 0..3
    const int lane = tid & 31;
    const int qb = (int)gridDim.x - 1 - (int)blockIdx.x;
    const int bh = blockIdx.y;
    const int b  = bh >> 4;
    const int h  = bh & 15;
    const int q0 = qb * 128;

    const size_t qgbase = (size_t)(b * S_LEN + q0) * D_MODEL + h * DK;
    const size_t kgbase = (size_t)(b * S_LEN) * D_MODEL + h * DK;

    auto issue_tile = [&](int stg, int kt) {
        const uint32_t sbase = sb + STG0 + stg * ASTG_B;
        const size_t g0 = kgbase + (size_t)(kt * 64) * D_MODEL;
#pragma unroll
        for (int it = 0; it < 4; it++) {
            int slot = tid + it * 128;         // 0..511
            int r  = slot >> 3;                // 0..63
            int c8 = (slot & 7) * 8;
            uint32_t soff = (uint32_t)(r * AROW + c8) * 2;
            const size_t go = g0 + (size_t)r * D_MODEL + c8;
            CP16(sbase + soff,         (const char*)(g_Kh + go));
            CP16(sbase + A_ARR + soff, (const char*)(g_Vh + go));
        }
    };

    const int ntiles = 2 * qb + 2;

    issue_tile(0, 0);
    CP_COMMIT();
    issue_tile(1, 1);
    CP_COMMIT();

    // load Q tile (128 rows)
#pragma unroll
    for (int it = 0; it < 8; it++) {
        int slot = tid + it * 128;             // 0..1023
        int r  = slot >> 3;                    // 0..127
        int c8 = (slot & 7) * 8;
        uint32_t soff = (uint32_t)(r * AROW + c8) * 2;
        const size_t go = qgbase + (size_t)r * D_MODEL + c8;
        *(uint4*)(smem + SQ_OFF + soff) = *(const uint4*)(g_Qh + go);
    }

    // two 16-row groups per warp: rows wid*32 and wid*32+16
    float oa0[8][4], oa1[8][4];
#pragma unroll
    for (int nt = 0; nt < 8; nt++)
#pragma unroll
        for (int j = 0; j < 4; j++) { oa0[nt][j] = 0.f; oa1[nt][j] = 0.f; }
    float m0 = -1e30f, m1 = -1e30f, m2 = -1e30f, m3 = -1e30f;
    float l0 = 0.f, l1 = 0.f, l2 = 0.f, l3 = 0.f;

    const int wrow_min = q0 + wid * 32;
    const int row_a = wrow_min + (lane >> 2);        // group0 rows (and +8)
    const int row_b = row_a + 16;                    // group1 rows (and +8)

    const uint32_t qBase0 = sb + SQ_OFF +
        (uint32_t)((wid * 32 + (lane & 15)) * AROW + ((lane >> 4) << 3)) * 2;
    const uint32_t qBase1 = qBase0 + (uint32_t)(16 * AROW) * 2;

    for (int kt = 0; kt < ntiles; kt++) {
        if (kt + 1 < ntiles) CP_WAIT1(); else CP_WAIT0();
        __syncthreads();
        if (kt + 2 < ntiles) { issue_tile((kt + 2) % 3, kt + 2); CP_COMMIT(); }

        if (kt * 64 > wrow_min + 31) continue;

        const uint32_t st = sb + STG0 + (kt % 3) * ASTG_B;

        float s0[8][4], s1[8][4];
#pragma unroll
        for (int nt = 0; nt < 8; nt++)
#pragma unroll
            for (int j = 0; j < 4; j++) { s0[nt][j] = 0.f; s1[nt][j] = 0.f; }

        // S = Q @ K^T for both row groups; each K fragment feeds 4 mma
#pragma unroll
        for (int t = 0; t < 4; t++) {
            uint32_t q0f[4], q1f[4];
            ldsm_x4(q0f, qBase0 + (uint32_t)(t * 16) * 2);
            ldsm_x4(q1f, qBase1 + (uint32_t)(t * 16) * 2);
#pragma unroll
            for (int g = 0; g < 4; g++) {
                uint32_t addr = st +
                    (uint32_t)((g * 16 + (lane & 15)) * AROW + t * 16 + ((lane >> 4) << 3)) * 2;
                uint32_t kh4[4];
                ldsm_x4(kh4, addr);
                mma_f16(s0[2 * g],     q0f, kh4[0], kh4[2]);
                mma_f16(s0[2 * g + 1], q0f, kh4[1], kh4[3]);
                mma_f16(s1[2 * g],     q1f, kh4[0], kh4[2]);
                mma_f16(s1[2 * g + 1], q1f, kh4[1], kh4[3]);
            }
        }

        if (kt * 64 + 63 > wrow_min) {
#pragma unroll
            for (int nt = 0; nt < 8; nt++) {
                int col = kt * 64 + nt * 8 + (lane & 3) * 2;
                if (col     > row_a)     s0[nt][0] = -1e30f;
                if (col + 1 > row_a)     s0[nt][1] = -1e30f;
                if (col     > row_a + 8) s0[nt][2] = -1e30f;
                if (col + 1 > row_a + 8) s0[nt][3] = -1e30f;
                if (col     > row_b)     s1[nt][0] = -1e30f;
                if (col + 1 > row_b)     s1[nt][1] = -1e30f;
                if (col     > row_b + 8) s1[nt][2] = -1e30f;
                if (col + 1 > row_b + 8) s1[nt][3] = -1e30f;
            }
        }

        // ---- online softmax, both groups ----
        float x0 = -1e30f, x1 = -1e30f, x2 = -1e30f, x3 = -1e30f;
#pragma unroll
        for (int nt = 0; nt < 8; nt++) {
            x0 = fmaxf(x0, fmaxf(s0[nt][0], s0[nt][1]));
            x1 = fmaxf(x1, fmaxf(s0[nt][2], s0[nt][3]));
            x2 = fmaxf(x2, fmaxf(s1[nt][0], s1[nt][1]));
            x3 = fmaxf(x3, fmaxf(s1[nt][2], s1[nt][3]));
        }
        x0 = fmaxf(x0, __shfl_xor_sync(0xffffffffu, x0, 1));
        x0 = fmaxf(x0, __shfl_xor_sync(0xffffffffu, x0, 2));
        x1 = fmaxf(x1, __shfl_xor_sync(0xffffffffu, x1, 1));
        x1 = fmaxf(x1, __shfl_xor_sync(0xffffffffu, x1, 2));
        x2 = fmaxf(x2, __shfl_xor_sync(0xffffffffu, x2, 1));
        x2 = fmaxf(x2, __shfl_xor_sync(0xffffffffu, x2, 2));
        x3 = fmaxf(x3, __shfl_xor_sync(0xffffffffu, x3, 1));
        x3 = fmaxf(x3, __shfl_xor_sync(0xffffffffu, x3, 2));

        float n0 = fmaxf(m0, x0), n1 = fmaxf(m1, x1);
        float n2 = fmaxf(m2, x2), n3 = fmaxf(m3, x3);
        float c0 = ex2f(m0 - n0), c1 = ex2f(m1 - n1);
        float c2 = ex2f(m2 - n2), c3 = ex2f(m3 - n3);
        m0 = n0; m1 = n1; m2 = n2; m3 = n3;

        float u0 = 0.f, u1 = 0.f, u2 = 0.f, u3 = 0.f;
#pragma unroll
        for (int nt = 0; nt < 8; nt++) {
            s0[nt][0] = ex2f(s0[nt][0] - n0);
            s0[nt][1] = ex2f(s0[nt][1] - n0);
            s0[nt][2] = ex2f(s0[nt][2] - n1);
            s0[nt][3] = ex2f(s0[nt][3] - n1);
            s1[nt][0] = ex2f(s1[nt][0] - n2);
            s1[nt][1] = ex2f(s1[nt][1] - n2);
            s1[nt][2] = ex2f(s1[nt][2] - n3);
            s1[nt][3] = ex2f(s1[nt][3] - n3);
            u0 += s0[nt][0] + s0[nt][1];
            u1 += s0[nt][2] + s0[nt][3];
            u2 += s1[nt][0] + s1[nt][1];
            u3 += s1[nt][2] + s1[nt][3];
        }
        u0 += __shfl_xor_sync(0xffffffffu, u0, 1);
        u0 += __shfl_xor_sync(0xffffffffu, u0, 2);
        u1 += __shfl_xor_sync(0xffffffffu, u1, 1);
        u1 += __shfl_xor_sync(0xffffffffu, u1, 2);
        u2 += __shfl_xor_sync(0xffffffffu, u2, 1);
        u2 += __shfl_xor_sync(0xffffffffu, u2, 2);
        u3 += __shfl_xor_sync(0xffffffffu, u3, 1);
        u3 += __shfl_xor_sync(0xffffffffu, u3, 2);
        l0 = l0 * c0 + u0;
        l1 = l1 * c1 + u1;
        l2 = l2 * c2 + u2;
        l3 = l3 * c3 + u3;

#pragma unroll
        for (int nt = 0; nt < 8; nt++) {
            oa0[nt][0] *= c0; oa0[nt][1] *= c0;
            oa0[nt][2] *= c1; oa0[nt][3] *= c1;
            oa1[nt][0] *= c2; oa1[nt][1] *= c2;
            oa1[nt][2] *= c3; oa1[nt][3] *= c3;
        }

        uint32_t p0[4][4], p1[4][4];
#pragma unroll
        for (int t = 0; t < 4; t++) {
            p0[t][0] = pack2h(s0[2 * t][0],     s0[2 * t][1]);
            p0[t][1] = pack2h(s0[2 * t][2],     s0[2 * t][3]);
            p0[t][2] = pack2h(s0[2 * t + 1][0], s0[2 * t + 1][1]);
            p0[t][3] = pack2h(s0[2 * t + 1][2], s0[2 * t + 1][3]);
            p1[t][0] = pack2h(s1[2 * t][0],     s1[2 * t][1]);
            p1[t][1] = pack2h(s1[2 * t][2],     s1[2 * t][3]);
            p1[t][2] = pack2h(s1[2 * t + 1][0], s1[2 * t + 1][1]);
            p1[t][3] = pack2h(s1[2 * t + 1][2], s1[2 * t + 1][3]);
        }

        // O += P @ V for both groups; each V fragment feeds 4 mma
#pragma unroll
        for (int t = 0; t < 4; t++) {
#pragma unroll
            for (int g = 0; g < 4; g++) {
                uint32_t addr = st + A_ARR +
                    (uint32_t)((t * 16 + (lane & 7) + ((lane >> 3) & 1) * 8) * AROW +
                               g * 16 + ((lane >> 4) << 3)) * 2;
                uint32_t vh4[4];
                ldsm_x4t(vh4, addr);
                mma_f16(oa0[2 * g],     p0[t], vh4[0], vh4[1]);
                mma_f16(oa0[2 * g + 1], p0[t], vh4[2], vh4[3]);
                mma_f16(oa1[2 * g],     p1[t], vh4[0], vh4[1]);
                mma_f16(oa1[2 * g + 1], p1[t], vh4[2], vh4[3]);
            }
        }
    }

    // ---- epilogue: normalize + fp16 to global (for out-proj) ----
    float i0 = 1.0f / l0, i1 = 1.0f / l1, i2 = 1.0f / l2, i3 = 1.0f / l3;
    size_t ba0 = (size_t)(b * S_LEN + row_a) * D_MODEL + h * DK;
    size_t ba1 = ba0 + (size_t)8 * D_MODEL;
    size_t bb0 = (size_t)(b * S_LEN + row_b) * D_MODEL + h * DK;
    size_t bb1 = bb0 + (size_t)8 * D_MODEL;
#pragma unroll
    for (int nt = 0; nt < 8; nt++) {
        int col = nt * 8 + (lane & 3) * 2;
        *(uint32_t*)(g_attnh + ba0 + col) = pack2h(oa0[nt][0] * i0, oa0[nt][1] * i0);
        *(uint32_t*)(g_attnh + ba1 + col) = pack2h(oa0[nt][2] * i1, oa0[nt][3] * i1);
        *(uint32_t*)(g_attnh + bb0 + col) = pack2h(oa1[nt][0] * i2, oa1[nt][1] * i2);
        *(uint32_t*)(g_attnh + bb1 + col) = pack2h(oa1[nt][2] * i3, oa1[nt][3] * i3);
    }
}

// ---------------- launch ------------------------------------------------------
extern "C" void kernel_launch(void* const* d_in, const int* in_sizes, int n_in,
                              void* d_out, int out_size)
{
    const float* x  = (const float*)d_in[0];
    const float* Wq = (const float*)d_in[1];
    const float* bq = (const float*)d_in[2];
    const float* Wk = (const float*)d_in[3];
    const float* bk = (const float*)d_in[4];
    const float* Wv = (const float*)d_in[5];
    const float* bv = (const float*)d_in[6];
    const float* Wo = (const float*)d_in[7];
    const float* bo = (const float*)d_in[8];
    float* out = (float*)d_out;

    static int configured = 0;
    if (!configured) {
        cudaFuncSetAttribute(tc_qkv_v6, cudaFuncAttributeMaxDynamicSharedMemorySize, GSMEM_TOTAL);
        cudaFuncSetAttribute(tc_out_v6, cudaFuncAttributeMaxDynamicSharedMemorySize, GSMEM_TOTAL);
        cudaFuncSetAttribute(attn_mma_kernel, cudaFuncAttributeMaxDynamicSharedMemorySize, A_SMEM);
        configured = 1;
    }

    // 0) fused rope table + fp16 casts of x and weights
    split_all<<<(2 * 1024 * 1024) / 256, 256>>>(x, Wq, Wk, Wv, Wo);

    // 1) QKV projections (single-product fp16, 3-stage ring) + RoPE epilogue
    dim3 g_qkv(D_MODEL / 128, M_TOT / 128, 3);
    tc_qkv_v6<<<g_qkv, 256, GSMEM_TOTAL>>>(bq, bk, bv);

    // 2) causal attention (4 warps x 32 rows, exp2 domain, 3-stage ring)
    dim3 g_att(S_LEN / 128, BATCH * NHEAD);
    attn_mma_kernel<<<g_att, 128, A_SMEM>>>();

    // 3) output projection (single-product fp16, 3-stage ring)
    dim3 g_out(D_MODEL / 128, M_TOT / 128);
    tc_out_v6<<<g_out, 256, GSMEM_TOTAL>>>(bo, out);
}

// round 16
// speedup vs baseline: 1.5674x; 1.0088x over previous
#include <cuda_runtime.h>
#include <cuda_bf16.h>
#include <cuda_fp16.h>
#include <math.h>
#include <stdint.h>

#define D_MODEL 1024
#define S_LEN   2048
#define BATCH   2
#define NHEAD   16
#define DK      64
#define M_TOT   (BATCH * S_LEN)   // 4096
#define QSCALE  0.1803368801111244f   // (1/8) * log2(e)

// ---------------- scratch (device globals; no allocations allowed) ----------
__device__ __half g_Xh[M_TOT * D_MODEL];
__device__ __half g_Wq[D_MODEL * D_MODEL];
__device__ __half g_Wk[D_MODEL * D_MODEL];
__device__ __half g_Wv[D_MODEL * D_MODEL];
__device__ __half g_Wo[D_MODEL * D_MODEL];
__device__ __half g_Qh [M_TOT * D_MODEL];
__device__ __half g_Kh [M_TOT * D_MODEL];
__device__ __half g_Vh [M_TOT * D_MODEL];
__device__ __half g_attnh[M_TOT * D_MODEL];
__device__ float g_cos[S_LEN * 32];
__device__ float g_sin[S_LEN * 32];

// ---------------- common helpers --------------------------------------------
__device__ __forceinline__ uint32_t smem_u32(const void* p) {
    uint32_t a;
    asm("{ .reg .u64 t; cvta.to.shared.u64 t, %1; cvt.u32.u64 %0, t; }" : "=r"(a) : "l"(p));
    return a;
}

__device__ __forceinline__ float ex2f(float x) {
    float y;
    asm("ex2.approx.f32 %0, %1;" : "=f"(y) : "f"(x));
    return y;
}

__device__ __forceinline__ void ldsm_x4(uint32_t* r, uint32_t addr) {
    asm volatile("ldmatrix.sync.aligned.m8n8.x4.shared.b16 {%0,%1,%2,%3}, [%4];"
                 : "=r"(r[0]), "=r"(r[1]), "=r"(r[2]), "=r"(r[3]) : "r"(addr));
}

__device__ __forceinline__ void ldsm_x4t(uint32_t* r, uint32_t addr) {
    asm volatile("ldmatrix.sync.aligned.m8n8.x4.trans.shared.b16 {%0,%1,%2,%3}, [%4];"
                 : "=r"(r[0]), "=r"(r[1]), "=r"(r[2]), "=r"(r[3]) : "r"(addr));
}

__device__ __forceinline__ void mma_f16(float* c, const uint32_t* a,
                                        uint32_t b0, uint32_t b1) {
    asm volatile("mma.sync.aligned.m16n8k16.row.col.f32.f16.f16.f32 "
                 "{%0,%1,%2,%3}, {%4,%5,%6,%7}, {%8,%9}, {%0,%1,%2,%3};"
                 : "+f"(c[0]), "+f"(c[1]), "+f"(c[2]), "+f"(c[3])
                 : "r"(a[0]), "r"(a[1]), "r"(a[2]), "r"(a[3]), "r"(b0), "r"(b1));
}

__device__ __forceinline__ uint32_t pack2h(float a, float b) {
    union { __half2 h; uint32_t u; } c;
    c.h = __halves2half2(__float2half_rn(a), __float2half_rn(b));
    return c.u;
}

#define CP16(saddr, gptr) \
    asm volatile("cp.async.cg.shared.global [%0], [%1], 16;" :: "r"(saddr), "l"(gptr))
#define CP_COMMIT() asm volatile("cp.async.commit_group;" ::: "memory")
#define CP_WAIT0()  asm volatile("cp.async.wait_group 0;" ::: "memory")
#define CP_WAIT1()  asm volatile("cp.async.wait_group 1;" ::: "memory")

// ---------------- fused rope table + fp16 casts ------------------------------
__global__ void split_all(const float* __restrict__ x,  const float* __restrict__ Wq,
                          const float* __restrict__ Wk, const float* __restrict__ Wv,
                          const float* __restrict__ Wo)
{
    int t = blockIdx.x * blockDim.x + threadIdx.x;   // 0..2M-1
    if (t < S_LEN * 32) {
        int s = t >> 5, i = t & 31;
        float inv_freq = __expf(-(float)(2 * i) * (9.210340371976184f / 64.0f));
        float ang = (float)s * inv_freq;
        g_cos[t] = cosf(ang);
        g_sin[t] = sinf(ang);
    }
    const float* src;
    __half* dst;
    size_t off;
    if (t < (1 << 20)) { src = x; dst = g_Xh; off = t; }
    else {
        int r = t - (1 << 20);
        int w = r >> 18;
        off = (size_t)(r & ((1 << 18) - 1));
        if      (w == 0) { src = Wq; dst = g_Wq; }
        else if (w == 1) { src = Wk; dst = g_Wk; }
        else if (w == 2) { src = Wv; dst = g_Wv; }
        else             { src = Wo; dst = g_Wo; }
    }
    float4 v = ((const float4*)src)[off];
    uint2 o;
    o.x = pack2h(v.x, v.y);
    o.y = pack2h(v.z, v.w);
    ((uint2*)dst)[off] = o;
}

// ========== fp16 single-product GEMM (BK=64, 3-stage cp.async ring) ==========
#define GBK 64
#define GCHUNKS (D_MODEL / GBK)           // 16
#define GROWH  72                         // 144B row stride, conflict-free
#define GARR_B (128 * GROWH * 2)          // 18432
#define GSTG_B (2 * GARR_B)               // 36864 (A, B)
#define GSMEM_TOTAL (3 * GSTG_B)          // 110592

__device__ __forceinline__ void gemm_v5_core(
    const __half* __restrict__ A, const __half* __restrict__ B,
    int bm, int bn, float (&acc)[4][4][4])
{
    extern __shared__ char smem[];
    const uint32_t sb = smem_u32(smem);
    const int tid  = threadIdx.x;
    const int wid  = tid >> 5;
    const int lane = tid & 31;
    const int warp_m = (wid >> 2) * 64;
    const int warp_n = (wid & 3) * 32;

#pragma unroll
    for (int i = 0; i < 4; i++)
#pragma unroll
        for (int j = 0; j < 4; j++)
#pragma unroll
            for (int k = 0; k < 4; k++) acc[i][j][k] = 0.f;

    auto issue = [&](int stg, int c) {
        const uint32_t st = sb + stg * GSTG_B;
        const int k0 = c * GBK;
#pragma unroll
        for (int it = 0; it < 4; it++) {
            int slot = tid + it * 256;            // 0..1023
            int r  = slot >> 3;                   // 0..127
            int c8 = (slot & 7) * 8;              // halves
            uint32_t soff = (uint32_t)(r * GROWH + c8) * 2;
            size_t ga = (size_t)(bm + r) * D_MODEL + k0 + c8;
            size_t gb = (size_t)(bn + r) * D_MODEL + k0 + c8;
            CP16(st + soff,          (const char*)(A + ga));
            CP16(st + GARR_B + soff, (const char*)(B + gb));
        }
    };

    issue(0, 0);
    CP_COMMIT();
    issue(1, 1);
    CP_COMMIT();

    const int qrow = lane & 15;
    const int qcol = (lane >> 4) << 3;

    for (int c = 0; c < GCHUNKS; c++) {
        if (c + 1 < GCHUNKS) CP_WAIT1(); else CP_WAIT0();
        __syncthreads();
        if (c + 2 < GCHUNKS) { issue((c + 2) % 3, c + 2); CP_COMMIT(); }

        const uint32_t st = sb + (c % 3) * GSTG_B;
        const uint32_t aBase = st + (uint32_t)((warp_m + qrow) * GROWH + qcol) * 2;
        const uint32_t bBase = st + GARR_B + (uint32_t)((warp_n + qrow) * GROWH + qcol) * 2;

#pragma unroll
        for (int ks = 0; ks < 4; ks++) {
            const uint32_t ko = (uint32_t)(ks * 16) * 2;
            uint32_t bf[2][4];
#pragma unroll
            for (int nt = 0; nt < 2; nt++)
                ldsm_x4(bf[nt], bBase + nt * (16 * GROWH * 2) + ko);
#pragma unroll
            for (int mi = 0; mi < 4; mi++) {
                uint32_t af[4];
                ldsm_x4(af, aBase + mi * (16 * GROWH * 2) + ko);
#pragma unroll
                for (int nt = 0; nt < 2; nt++)
#pragma unroll
                    for (int nj = 0; nj < 2; nj++)
                        mma_f16(acc[mi][nt * 2 + nj], af, bf[nt][nj], bf[nt][nj + 2]);
            }
        }
    }
}

// QKV GEMM: fused bias + RoPE; Q (log2e-scaled), K, V -> plain fp16
// __launch_bounds__(256,1): 255-reg budget so ptxas can hoist ldsm prefetches.
__global__ __launch_bounds__(256, 1)
void tc_qkv_v8(const float* __restrict__ bq, const float* __restrict__ bk,
               const float* __restrict__ bv)
{
    const int z = blockIdx.z;
    const __half* W;
    const float* bias;
    __half* D;
    if (z == 0)      { W = g_Wq; bias = bq; D = g_Qh; }
    else if (z == 1) { W = g_Wk; bias = bk; D = g_Kh; }
    else             { W = g_Wv; bias = bv; D = g_Vh; }

    const int bm = blockIdx.y * 128;
    const int bn = blockIdx.x * 128;
    float acc[4][4][4];
    gemm_v5_core(g_Xh, W, bm, bn, acc);

    const int wid  = threadIdx.x >> 5;
    const int lane = threadIdx.x & 31;
    const int warp_m = (wid >> 2) * 64;
    const int warp_n = (wid & 3) * 32;
    const int erow = lane >> 2;
    const int ecol = (lane & 3) * 2;

#pragma unroll
    for (int mi = 0; mi < 4; mi++)
#pragma unroll
        for (int nt = 0; nt < 2; nt++)
#pragma unroll
            for (int nj = 0; nj < 2; nj++) {
                float* cc = acc[mi][nt * 2 + nj];
                int m = bm + warp_m + mi * 16 + erow;
                int n = bn + warp_n + nt * 16 + nj * 8 + ecol;
                float v0 = cc[0] + bias[n], v1 = cc[1] + bias[n + 1];
                float w0 = cc[2] + bias[n], w1 = cc[3] + bias[n + 1];
                if (z < 2) {
                    int i  = (n & 63) >> 1;
                    int s0 = (m & 2047) * 32 + i;
                    int s1 = ((m + 8) & 2047) * 32 + i;
                    float cs0 = g_cos[s0], sn0 = g_sin[s0];
                    float cs1 = g_cos[s1], sn1 = g_sin[s1];
                    float t0 = v0 * cs0 - v1 * sn0, t1 = v0 * sn0 + v1 * cs0;
                    float u0 = w0 * cs1 - w1 * sn1, u1 = w0 * sn1 + w1 * cs1;
                    if (z == 0) { t0 *= QSCALE; t1 *= QSCALE; u0 *= QSCALE; u1 *= QSCALE; }
                    v0 = t0; v1 = t1; w0 = u0; w1 = u1;
                }
                size_t o0 = (size_t)m * D_MODEL + n;
                size_t o1 = (size_t)(m + 8) * D_MODEL + n;
                *(uint32_t*)(D + o0) = pack2h(v0, v1);
                *(uint32_t*)(D + o1) = pack2h(w0, w1);
            }
}

__global__ __launch_bounds__(256, 1)
void tc_out_v8(const float* __restrict__ bo, float* __restrict__ out)
{
    const int bm = blockIdx.y * 128;
    const int bn = blockIdx.x * 128;
    float acc[4][4][4];
    gemm_v5_core(g_attnh, g_Wo, bm, bn, acc);

    const int wid  = threadIdx.x >> 5;
    const int lane = threadIdx.x & 31;
    const int warp_m = (wid >> 2) * 64;
    const int warp_n = (wid & 3) * 32;
    const int erow = lane >> 2;
    const int ecol = (lane & 3) * 2;

#pragma unroll
    for (int mi = 0; mi < 4; mi++)
#pragma unroll
        for (int nt = 0; nt < 2; nt++)
#pragma unroll
            for (int nj = 0; nj < 2; nj++) {
                float* cc = acc[mi][nt * 2 + nj];
                int m = bm + warp_m + mi * 16 + erow;
                int n = bn + warp_n + nt * 16 + nj * 8 + ecol;
                float2 v0 = make_float2(cc[0] + bo[n], cc[1] + bo[n + 1]);
                float2 v1 = make_float2(cc[2] + bo[n], cc[3] + bo[n + 1]);
                *(float2*)(out + (size_t)m * D_MODEL + n)       = v0;
                *(float2*)(out + (size_t)(m + 8) * D_MODEL + n) = v1;
            }
}

// ---- attention: 4 warps x 32 rows, single fp16 Q, 3-stage ring --------------
// l kept per-lane; cross-lane reduction deferred to epilogue (corr is
// row-uniform after the max shuffle, so per-lane accumulation is exact).
#define AROW   72
#define A_ARR  (64 * AROW * 2)            // 9216
#define AQ_ARR (128 * AROW * 2)           // 18432
#define SQ_OFF 0
#define STG0   AQ_ARR                     // 18432
#define ASTG_B (2 * A_ARR)                // 18432 (Kh, Vh)
#define A_SMEM (AQ_ARR + 3 * ASTG_B)      // 73728

__global__ __launch_bounds__(128, 3)
void attn_mma_kernel()
{
    extern __shared__ char smem[];
    const uint32_t sb = smem_u32(smem);
    const int tid  = threadIdx.x;
    const int wid  = tid >> 5;                 // 0..3
    const int lane = tid & 31;
    const int qb = (int)gridDim.x - 1 - (int)blockIdx.x;
    const int bh = blockIdx.y;
    const int b  = bh >> 4;
    const int h  = bh & 15;
    const int q0 = qb * 128;

    const size_t qgbase = (size_t)(b * S_LEN + q0) * D_MODEL + h * DK;
    const size_t kgbase = (size_t)(b * S_LEN) * D_MODEL + h * DK;

    auto issue_tile = [&](int stg, int kt) {
        const uint32_t sbase = sb + STG0 + stg * ASTG_B;
        const size_t g0 = kgbase + (size_t)(kt * 64) * D_MODEL;
#pragma unroll
        for (int it = 0; it < 4; it++) {
            int slot = tid + it * 128;         // 0..511
            int r  = slot >> 3;                // 0..63
            int c8 = (slot & 7) * 8;
            uint32_t soff = (uint32_t)(r * AROW + c8) * 2;
            const size_t go = g0 + (size_t)r * D_MODEL + c8;
            CP16(sbase + soff,         (const char*)(g_Kh + go));
            CP16(sbase + A_ARR + soff, (const char*)(g_Vh + go));
        }
    };

    const int ntiles = 2 * qb + 2;

    issue_tile(0, 0);
    CP_COMMIT();
    issue_tile(1, 1);
    CP_COMMIT();

    // load Q tile (128 rows)
#pragma unroll
    for (int it = 0; it < 8; it++) {
        int slot = tid + it * 128;             // 0..1023
        int r  = slot >> 3;                    // 0..127
        int c8 = (slot & 7) * 8;
        uint32_t soff = (uint32_t)(r * AROW + c8) * 2;
        const size_t go = qgbase + (size_t)r * D_MODEL + c8;
        *(uint4*)(smem + SQ_OFF + soff) = *(const uint4*)(g_Qh + go);
    }

    // two 16-row groups per warp: rows wid*32 and wid*32+16
    float oa0[8][4], oa1[8][4];
#pragma unroll
    for (int nt = 0; nt < 8; nt++)
#pragma unroll
        for (int j = 0; j < 4; j++) { oa0[nt][j] = 0.f; oa1[nt][j] = 0.f; }
    float m0 = -1e30f, m1 = -1e30f, m2 = -1e30f, m3 = -1e30f;
    float l0 = 0.f, l1 = 0.f, l2 = 0.f, l3 = 0.f;   // per-lane partials

    const int wrow_min = q0 + wid * 32;
    const int row_a = wrow_min + (lane >> 2);        // group0 rows (and +8)
    const int row_b = row_a + 16;                    // group1 rows (and +8)

    const uint32_t qBase0 = sb + SQ_OFF +
        (uint32_t)((wid * 32 + (lane & 15)) * AROW + ((lane >> 4) << 3)) * 2;
    const uint32_t qBase1 = qBase0 + (uint32_t)(16 * AROW) * 2;

    for (int kt = 0; kt < ntiles; kt++) {
        if (kt + 1 < ntiles) CP_WAIT1(); else CP_WAIT0();
        __syncthreads();
        if (kt + 2 < ntiles) { issue_tile((kt + 2) % 3, kt + 2); CP_COMMIT(); }

        if (kt * 64 > wrow_min + 31) continue;

        const uint32_t st = sb + STG0 + (kt % 3) * ASTG_B;

        float s0[8][4], s1[8][4];
#pragma unroll
        for (int nt = 0; nt < 8; nt++)
#pragma unroll
            for (int j = 0; j < 4; j++) { s0[nt][j] = 0.f; s1[nt][j] = 0.f; }

        // S = Q @ K^T for both row groups; each K fragment feeds 4 mma
#pragma unroll
        for (int t = 0; t < 4; t++) {
            uint32_t q0f[4], q1f[4];
            ldsm_x4(q0f, qBase0 + (uint32_t)(t * 16) * 2);
            ldsm_x4(q1f, qBase1 + (uint32_t)(t * 16) * 2);
#pragma unroll
            for (int g = 0; g < 4; g++) {
                uint32_t addr = st +
                    (uint32_t)((g * 16 + (lane & 15)) * AROW + t * 16 + ((lane >> 4) << 3)) * 2;
                uint32_t kh4[4];
                ldsm_x4(kh4, addr);
                mma_f16(s0[2 * g],     q0f, kh4[0], kh4[2]);
                mma_f16(s0[2 * g + 1], q0f, kh4[1], kh4[3]);
                mma_f16(s1[2 * g],     q1f, kh4[0], kh4[2]);
                mma_f16(s1[2 * g + 1], q1f, kh4[1], kh4[3]);
            }
        }

        if (kt * 64 + 63 > wrow_min) {
#pragma unroll
            for (int nt = 0; nt < 8; nt++) {
                int col = kt * 64 + nt * 8 + (lane & 3) * 2;
                if (col     > row_a)     s0[nt][0] = -1e30f;
                if (col + 1 > row_a)     s0[nt][1] = -1e30f;
                if (col     > row_a + 8) s0[nt][2] = -1e30f;
                if (col + 1 > row_a + 8) s0[nt][3] = -1e30f;
                if (col     > row_b)     s1[nt][0] = -1e30f;
                if (col + 1 > row_b)     s1[nt][1] = -1e30f;
                if (col     > row_b + 8) s1[nt][2] = -1e30f;
                if (col + 1 > row_b + 8) s1[nt][3] = -1e30f;
            }
        }

        // ---- online softmax, both groups (row max shuffled; l per-lane) ----
        float x0 = -1e30f, x1 = -1e30f, x2 = -1e30f, x3 = -1e30f;
#pragma unroll
        for (int nt = 0; nt < 8; nt++) {
            x0 = fmaxf(x0, fmaxf(s0[nt][0], s0[nt][1]));
            x1 = fmaxf(x1, fmaxf(s0[nt][2], s0[nt][3]));
            x2 = fmaxf(x2, fmaxf(s1[nt][0], s1[nt][1]));
            x3 = fmaxf(x3, fmaxf(s1[nt][2], s1[nt][3]));
        }
        x0 = fmaxf(x0, __shfl_xor_sync(0xffffffffu, x0, 1));
        x0 = fmaxf(x0, __shfl_xor_sync(0xffffffffu, x0, 2));
        x1 = fmaxf(x1, __shfl_xor_sync(0xffffffffu, x1, 1));
        x1 = fmaxf(x1, __shfl_xor_sync(0xffffffffu, x1, 2));
        x2 = fmaxf(x2, __shfl_xor_sync(0xffffffffu, x2, 1));
        x2 = fmaxf(x2, __shfl_xor_sync(0xffffffffu, x2, 2));
        x3 = fmaxf(x3, __shfl_xor_sync(0xffffffffu, x3, 1));
        x3 = fmaxf(x3, __shfl_xor_sync(0xffffffffu, x3, 2));

        float n0 = fmaxf(m0, x0), n1 = fmaxf(m1, x1);
        float n2 = fmaxf(m2, x2), n3 = fmaxf(m3, x3);
        float c0 = ex2f(m0 - n0), c1 = ex2f(m1 - n1);
        float c2 = ex2f(m2 - n2), c3 = ex2f(m3 - n3);
        m0 = n0; m1 = n1; m2 = n2; m3 = n3;

        float u0 = 0.f, u1 = 0.f, u2 = 0.f, u3 = 0.f;
#pragma unroll
        for (int nt = 0; nt < 8; nt++) {
            s0[nt][0] = ex2f(s0[nt][0] - n0);
            s0[nt][1] = ex2f(s0[nt][1] - n0);
            s0[nt][2] = ex2f(s0[nt][2] - n1);
            s0[nt][3] = ex2f(s0[nt][3] - n1);
            s1[nt][0] = ex2f(s1[nt][0] - n2);
            s1[nt][1] = ex2f(s1[nt][1] - n2);
            s1[nt][2] = ex2f(s1[nt][2] - n3);
            s1[nt][3] = ex2f(s1[nt][3] - n3);
            u0 += s0[nt][0] + s0[nt][1];
            u1 += s0[nt][2] + s0[nt][3];
            u2 += s1[nt][0] + s1[nt][1];
            u3 += s1[nt][2] + s1[nt][3];
        }
        // per-lane l update; cross-lane reduce deferred to epilogue
        l0 = l0 * c0 + u0;
        l1 = l1 * c1 + u1;
        l2 = l2 * c2 + u2;
        l3 = l3 * c3 + u3;

#pragma unroll
        for (int nt = 0; nt < 8; nt++) {
            oa0[nt][0] *= c0; oa0[nt][1] *= c0;
            oa0[nt][2] *= c1; oa0[nt][3] *= c1;
            oa1[nt][0] *= c2; oa1[nt][1] *= c2;
            oa1[nt][2] *= c3; oa1[nt][3] *= c3;
        }

        uint32_t p0[4][4], p1[4][4];
#pragma unroll
        for (int t = 0; t < 4; t++) {
            p0[t][0] = pack2h(s0[2 * t][0],     s0[2 * t][1]);
            p0[t][1] = pack2h(s0[2 * t][2],     s0[2 * t][3]);
            p0[t][2] = pack2h(s0[2 * t + 1][0], s0[2 * t + 1][1]);
            p0[t][3] = pack2h(s0[2 * t + 1][2], s0[2 * t + 1][3]);
            p1[t][0] = pack2h(s1[2 * t][0],     s1[2 * t][1]);
            p1[t][1] = pack2h(s1[2 * t][2],     s1[2 * t][3]);
            p1[t][2] = pack2h(s1[2 * t + 1][0], s1[2 * t + 1][1]);
            p1[t][3] = pack2h(s1[2 * t + 1][2], s1[2 * t + 1][3]);
        }

        // O += P @ V for both groups; each V fragment feeds 4 mma
#pragma unroll
        for (int t = 0; t < 4; t++) {
#pragma unroll
            for (int g = 0; g < 4; g++) {
                uint32_t addr = st + A_ARR +
                    (uint32_t)((t * 16 + (lane & 7) + ((lane >> 3) & 1) * 8) * AROW +
                               g * 16 + ((lane >> 4) << 3)) * 2;
                uint32_t vh4[4];
                ldsm_x4t(vh4, addr);
                mma_f16(oa0[2 * g],     p0[t], vh4[0], vh4[1]);
                mma_f16(oa0[2 * g + 1], p0[t], vh4[2], vh4[3]);
                mma_f16(oa1[2 * g],     p1[t], vh4[0], vh4[1]);
                mma_f16(oa1[2 * g + 1], p1[t], vh4[2], vh4[3]);
            }
        }
    }

    // ---- epilogue: cross-lane l reduction, normalize, store fp16 ----
    l0 += __shfl_xor_sync(0xffffffffu, l0, 1);
    l0 += __shfl_xor_sync(0xffffffffu, l0, 2);
    l1 += __shfl_xor_sync(0xffffffffu, l1, 1);
    l1 += __shfl_xor_sync(0xffffffffu, l1, 2);
    l2 += __shfl_xor_sync(0xffffffffu, l2, 1);
    l2 += __shfl_xor_sync(0xffffffffu, l2, 2);
    l3 += __shfl_xor_sync(0xffffffffu, l3, 1);
    l3 += __shfl_xor_sync(0xffffffffu, l3, 2);
    float i0 = 1.0f / l0, i1 = 1.0f / l1, i2 = 1.0f / l2, i3 = 1.0f / l3;
    size_t ba0 = (size_t)(b * S_LEN + row_a) * D_MODEL + h * DK;
    size_t ba1 = ba0 + (size_t)8 * D_MODEL;
    size_t bb0 = (size_t)(b * S_LEN + row_b) * D_MODEL + h * DK;
    size_t bb1 = bb0 + (size_t)8 * D_MODEL;
#pragma unroll
    for (int nt = 0; nt < 8; nt++) {
        int col = nt * 8 + (lane & 3) * 2;
        *(uint32_t*)(g_attnh + ba0 + col) = pack2h(oa0[nt][0] * i0, oa0[nt][1] * i0);
        *(uint32_t*)(g_attnh + ba1 + col) = pack2h(oa0[nt][2] * i1, oa0[nt][3] * i1);
        *(uint32_t*)(g_attnh + bb0 + col) = pack2h(oa1[nt][0] * i2, oa1[nt][1] * i2);
        *(uint32_t*)(g_attnh + bb1 + col) = pack2h(oa1[nt][2] * i3, oa1[nt][3] * i3);
    }
}

// ---------------- launch ------------------------------------------------------
extern "C" void kernel_launch(void* const* d_in, const int* in_sizes, int n_in,
                              void* d_out, int out_size)
{
    const float* x  = (const float*)d_in[0];
    const float* Wq = (const float*)d_in[1];
    const float* bq = (const float*)d_in[2];
    const float* Wk = (const float*)d_in[3];
    const float* bk = (const float*)d_in[4];
    const float* Wv = (const float*)d_in[5];
    const float* bv = (const float*)d_in[6];
    const float* Wo = (const float*)d_in[7];
    const float* bo = (const float*)d_in[8];
    float* out = (float*)d_out;

    static int configured = 0;
    if (!configured) {
        cudaFuncSetAttribute(tc_qkv_v8, cudaFuncAttributeMaxDynamicSharedMemorySize, GSMEM_TOTAL);
        cudaFuncSetAttribute(tc_out_v8, cudaFuncAttributeMaxDynamicSharedMemorySize, GSMEM_TOTAL);
        cudaFuncSetAttribute(attn_mma_kernel, cudaFuncAttributeMaxDynamicSharedMemorySize, A_SMEM);
        configured = 1;
    }

    // 0) fused rope table + fp16 casts of x and weights
    split_all<<<(2 * 1024 * 1024) / 256, 256>>>(x, Wq, Wk, Wv, Wo);

    // 1) QKV projections (single-product fp16, 255-reg budget) + RoPE epilogue
    dim3 g_qkv(D_MODEL / 128, M_TOT / 128, 3);
    tc_qkv_v8<<<g_qkv, 256, GSMEM_TOTAL>>>(bq, bk, bv);

    // 2) causal attention (4 warps x 32 rows, deferred-l softmax)
    dim3 g_att(S_LEN / 128, BATCH * NHEAD);
    attn_mma_kernel<<<g_att, 128, A_SMEM>>>();

    // 3) output projection (single-product fp16, 255-reg budget)
    dim3 g_out(D_MODEL / 128, M_TOT / 128);
    tc_out_v8<<<g_out, 256, GSMEM_TOTAL>>>(bo, out);
}